// round 1
// baseline (speedup 1.0000x reference)
#include <cuda_runtime.h>

// Problem constants
#define BB 4
#define TT 16
#define NN 512
#define FF 5
#define HH 64
#define SS 2048      // B*N sequences
#define RR 824
#define GG 256       // 4*H gates
#define R4 (RR/4)    // 206 float4 per relation row

// Scratch (device globals; no allocation allowed)
__device__ float g_relw[NN * NN];   // leaky(enc . fc1_w + fc1_b)  [n,m]
__device__ float g_tail[SS];        // leaky(out . fc3_w + fc3_b)
__device__ float g_q[SS];           // out . pred_w[64:128]
__device__ float g_p0[SS];          // out . pred_w[0:64]

__device__ __forceinline__ float leaky(float v) { return v > 0.f ? v : 0.01f * v; }
__device__ __forceinline__ float sigm(float v)  { return 1.f / (1.f + expf(-v)); }

// ---------------------------------------------------------------------------
// K1: rel_weight[n,m] = leaky(dot(enc[n,m,:], fc1_w) + fc1_b)
// One warp per (n,m) pair. Streams 863 MB — HBM-bound, the dominant kernel.
// ---------------------------------------------------------------------------
__global__ __launch_bounds__(256) void relw_kernel(const float* __restrict__ enc,
                                                   const float* __restrict__ fc1_w,
                                                   const float* __restrict__ fc1_b) {
    __shared__ float4 wsm[R4];
    int tid = threadIdx.x;
    const float4* w4 = (const float4*)fc1_w;
    for (int i = tid; i < R4; i += 256) wsm[i] = w4[i];
    __syncthreads();

    int warp = tid >> 5, lane = tid & 31;
    int pair = blockIdx.x * 8 + warp;                 // < 262144
    const float4* row = (const float4*)enc + (long long)pair * R4;

    float acc = 0.f;
    for (int i = lane; i < R4; i += 32) {             // 7 iters (last partial)
        float4 v = __ldcs(row + i);                   // evict-first streaming
        float4 w = wsm[i];
        acc += v.x * w.x + v.y * w.y + v.z * w.z + v.w * w.w;
    }
#pragma unroll
    for (int o = 16; o; o >>= 1) acc += __shfl_xor_sync(0xffffffffu, acc, o);
    if (lane == 0) g_relw[pair] = leaky(acc + fc1_b[0]);
}

// ---------------------------------------------------------------------------
// K2: per-sequence LSTM (16 fwd steps + 1 bwd step from zero state) fused with
// fc0, fc3(tail), and the pred_w dot-products.
// One CTA per sequence; thread = gate; Whh row register-resident.
// ---------------------------------------------------------------------------
__global__ __launch_bounds__(256, 2) void lstm_kernel(
    const float* __restrict__ x,
    const float* __restrict__ Wih_f, const float* __restrict__ Whh_f,
    const float* __restrict__ bih_f, const float* __restrict__ bhh_f,
    const float* __restrict__ Wih_b,
    const float* __restrict__ bih_b, const float* __restrict__ bhh_b,
    const float* __restrict__ fc0_w, const float* __restrict__ fc0_b,
    const float* __restrict__ fc3_w, const float* __restrict__ fc3_b,
    const float* __restrict__ pred_w, const float* __restrict__ pred_b)
{
    __shared__ float xs[TT * FF];          // 80
    __shared__ float sh_h[HH];             // hidden state
    __shared__ float arr[GG];              // activated gates
    __shared__ float last[2 * HH];         // [h_fwd_last, h_bwd_first]
    __shared__ float fc0wT[128 * 65];      // transposed, padded (conflict-free)
    __shared__ float out_sm[HH];

    int s = blockIdx.x;
    int b = s >> 9, n = s & (NN - 1);
    int tid = threadIdx.x;
    int g = tid;                            // gate index 0..255

    // Load the 16x5 input slice for this sequence: new_x[s,t,f] = x[b,t,n,f]
    if (tid < TT * FF) {
        int t = tid / FF, f = tid - t * FF;
        xs[tid] = x[((b * TT + t) * NN + n) * FF + f];
    }
    if (tid < HH) sh_h[tid] = 0.f;

    // fc0_w [64,128] -> fc0wT[k*65 + o]  (both STS and later LDS conflict-free)
    for (int i = tid; i < HH * 2 * HH; i += 256) {
        int o = i >> 7, k = i & 127;
        fc0wT[k * 65 + o] = fc0_w[i];
    }

    // Per-thread forward weights
    float wf[FF];
#pragma unroll
    for (int j = 0; j < FF; j++) wf[j] = Wih_f[g * FF + j];
    float bf = bih_f[g] + bhh_f[g];
    float wh[HH];
#pragma unroll
    for (int j = 0; j < HH / 4; j++) {
        float4 v = ((const float4*)Whh_f)[g * (HH / 4) + j];
        wh[4 * j] = v.x; wh[4 * j + 1] = v.y; wh[4 * j + 2] = v.z; wh[4 * j + 3] = v.w;
    }
    float c = 0.f;
    int gtype = g >> 6;   // 0=i 1=f 2=g 3=o  (per-warp uniform -> no divergence)
    __syncthreads();

    // ---- forward recurrence, 16 steps ----
    for (int t = 0; t < TT; t++) {
        float acc = bf;
#pragma unroll
        for (int j = 0; j < FF; j++) acc += xs[t * FF + j] * wf[j];
#pragma unroll
        for (int k = 0; k < HH; k++) acc += sh_h[k] * wh[k];
        arr[g] = (gtype == 2) ? tanhf(acc) : sigm(acc);
        __syncthreads();
        if (tid < HH) {
            float gi = arr[tid], gf = arr[HH + tid];
            float gc = arr[2 * HH + tid], go = arr[3 * HH + tid];
            c = gf * c + gi * gc;
            sh_h[tid] = go * tanhf(c);
        }
        __syncthreads();
    }
    if (tid < HH) last[tid] = sh_h[tid];

    // ---- backward LSTM: only hs_b[0] is consumed -> single step, zero state ----
    {
        float acc = bih_b[g] + bhh_b[g];
#pragma unroll
        for (int j = 0; j < FF; j++) acc += xs[(TT - 1) * FF + j] * Wih_b[g * FF + j];
        arr[g] = (gtype == 2) ? tanhf(acc) : sigm(acc);
    }
    __syncthreads();
    if (tid < HH) {
        float gi = arr[tid], gc = arr[2 * HH + tid], go = arr[3 * HH + tid];
        float cb = gi * gc;                  // f*c0 = 0
        last[HH + tid] = go * tanhf(cb);
    }
    __syncthreads();

    // ---- fc0 + leaky ----
    if (tid < HH) {
        float acc = fc0_b[tid];
#pragma unroll
        for (int k = 0; k < 2 * HH; k++) acc += last[k] * fc0wT[k * 65 + tid];
        out_sm[tid] = leaky(acc);
    }
    __syncthreads();

    // ---- fold the epilogue into scalars: tail, q, p0 ----
    int wid = tid >> 5, lane = tid & 31;
    if (wid < 3) {
        const float* w = (wid == 0) ? fc3_w : (wid == 1) ? (pred_w + HH) : pred_w;
        float v = out_sm[lane] * w[lane] + out_sm[lane + 32] * w[lane + 32];
#pragma unroll
        for (int o = 16; o; o >>= 1) v += __shfl_xor_sync(0xffffffffu, v, o);
        if (lane == 0) {
            if      (wid == 0) g_tail[s] = leaky(v + fc3_b[0]);
            else if (wid == 1) g_q[s]    = v;           // raw dot (no leaky)
            else               g_p0[s]   = v;           // raw dot (no leaky)
        }
    }
}

// ---------------------------------------------------------------------------
// K3: masked softmax over m + weighted sum of q  ->  prediction[b,n]
// head[b,n] is constant over m and cancels inside softmax (fc2 is dead).
// proped never materializes: pred = leaky(p0 + (Σ e^l q)/(Σ e^l) + pred_b).
// One warp per (b,n) row of 512.
// ---------------------------------------------------------------------------
__global__ __launch_bounds__(256) void prop_kernel(
    const float* __restrict__ rel_mask,
    const float* __restrict__ pred_b,
    float* __restrict__ out)
{
    __shared__ float tail_sm[NN];
    __shared__ float q_sm[NN];
    int b = blockIdx.y;
    int tid = threadIdx.x;
    for (int i = tid; i < NN; i += 256) {
        tail_sm[i] = g_tail[b * NN + i];
        q_sm[i]    = g_q[b * NN + i];
    }
    __syncthreads();

    int wid = tid >> 5, lane = tid & 31;
    int n = blockIdx.x * 8 + wid;
    const float* mrow = rel_mask + n * NN;
    const float* rrow = g_relw  + n * NN;

    float l[NN / 32];
    float mx = -1e30f;
#pragma unroll
    for (int j = 0; j < NN / 32; j++) {
        int m = j * 32 + lane;
        float v = mrow[m] + rrow[m] + tail_sm[m];
        l[j] = v;
        mx = fmaxf(mx, v);
    }
#pragma unroll
    for (int o = 16; o; o >>= 1) mx = fmaxf(mx, __shfl_xor_sync(0xffffffffu, mx, o));

    float se = 0.f, sq = 0.f;
#pragma unroll
    for (int j = 0; j < NN / 32; j++) {
        int m = j * 32 + lane;
        float e = __expf(l[j] - mx);
        se += e;
        sq += e * q_sm[m];
    }
#pragma unroll
    for (int o = 16; o; o >>= 1) {
        se += __shfl_xor_sync(0xffffffffu, se, o);
        sq += __shfl_xor_sync(0xffffffffu, sq, o);
    }
    if (lane == 0)
        out[b * NN + n] = leaky(g_p0[b * NN + n] + sq / se + pred_b[0]);
}

// ---------------------------------------------------------------------------
extern "C" void kernel_launch(void* const* d_in, const int* in_sizes, int n_in,
                              void* d_out, int out_size) {
    const float* x      = (const float*)d_in[0];
    const float* enc    = (const float*)d_in[1];
    const float* mask   = (const float*)d_in[2];
    const float* Wih_f  = (const float*)d_in[3];
    const float* Whh_f  = (const float*)d_in[4];
    const float* bih_f  = (const float*)d_in[5];
    const float* bhh_f  = (const float*)d_in[6];
    const float* Wih_b  = (const float*)d_in[7];
    // d_in[8] (Whh_b) unused: backward LSTM runs exactly one step from zero state
    const float* bih_b  = (const float*)d_in[9];
    const float* bhh_b  = (const float*)d_in[10];
    const float* fc0_w  = (const float*)d_in[11];
    const float* fc0_b  = (const float*)d_in[12];
    const float* fc1_w  = (const float*)d_in[13];
    const float* fc1_b  = (const float*)d_in[14];
    // d_in[15..16] (fc2) unused: head term is constant over softmax axis
    const float* fc3_w  = (const float*)d_in[17];
    const float* fc3_b  = (const float*)d_in[18];
    const float* pred_w = (const float*)d_in[19];
    const float* pred_b = (const float*)d_in[20];
    float* out = (float*)d_out;

    lstm_kernel<<<SS, 256>>>(x, Wih_f, Whh_f, bih_f, bhh_f, Wih_b, bih_b, bhh_b,
                             fc0_w, fc0_b, fc3_w, fc3_b, pred_w, pred_b);
    relw_kernel<<<NN * NN / 8, 256>>>(enc, fc1_w, fc1_b);
    prop_kernel<<<dim3(NN / 8, BB), 256>>>(mask, pred_b, out);
}